// round 2
// baseline (speedup 1.0000x reference)
#include <cuda_runtime.h>
#include <math.h>

#define TT 512
#define BB 64
#define EE 256
#define HH 200
#define G4 800
#define CC 20
#define NBD 50   // blocks per direction in LSTM kernel
#define HSL 4    // h-units per block (HH / NBD)

// ---------------- device scratch (no allocations allowed) ----------------
__device__ float d_x[TT * BB * EE];            // LN'd embeddings, [tok=t*64+b][e]
__device__ float d_G[2 * TT * G4 * BB];        // gates_x [dir][t][gate_row][b]
__device__ float d_hall[TT * BB * 2 * HH];     // h states [t][b][dir*H + j]
__device__ float d_hbuf[2 * 2 * HH * BB];      // h double buffer [dir][phase][j][b]
__device__ float d_logits[BB * TT * CC];       // log_softmax outputs [b][t][c]
__device__ float d_loss[BB];
__device__ unsigned d_bar[2];                  // per-direction phase-count barrier

__device__ __forceinline__ float sigf(float x) { return 1.f / (1.f + expf(-x)); }

// ---------------- K0: init ----------------
__global__ void k0_init() {
    int tid = threadIdx.x;
    for (int i = tid; i < 2 * 2 * HH * BB; i += 256) d_hbuf[i] = 0.f;
    if (tid < 2) d_bar[tid] = 0u;
}

// ---------------- K1: embedding + LayerNorm (warp per token) ----------------
__global__ void __launch_bounds__(256) k1_embed_ln(
    const int* __restrict__ words, const float* __restrict__ embed,
    const float* __restrict__ gamma, const float* __restrict__ beta)
{
    int wid = threadIdx.x >> 5, lane = threadIdx.x & 31;
    int tok = blockIdx.x * 8 + wid;          // tok = t*64 + b
    int t = tok >> 6, b = tok & 63;
    int word = words[b * TT + t];
    const float4* src = (const float4*)(embed + (size_t)word * EE);
    float4 v0 = src[lane * 2], v1 = src[lane * 2 + 1];
    float s = v0.x + v0.y + v0.z + v0.w + v1.x + v1.y + v1.z + v1.w;
    float q = v0.x*v0.x + v0.y*v0.y + v0.z*v0.z + v0.w*v0.w
            + v1.x*v1.x + v1.y*v1.y + v1.z*v1.z + v1.w*v1.w;
    #pragma unroll
    for (int o = 16; o; o >>= 1) {
        s += __shfl_xor_sync(~0u, s, o);
        q += __shfl_xor_sync(~0u, q, o);
    }
    float mu  = s * (1.f / EE);
    float var = q * (1.f / EE) - mu * mu;
    float rs  = rsqrtf(var + 1e-5f);
    const float4* g4 = (const float4*)gamma;
    const float4* bt4 = (const float4*)beta;
    float4 ga = g4[lane*2], gb = g4[lane*2+1];
    float4 ba = bt4[lane*2], bb = bt4[lane*2+1];
    float4 o0, o1;
    o0.x = (v0.x-mu)*rs*ga.x + ba.x;  o0.y = (v0.y-mu)*rs*ga.y + ba.y;
    o0.z = (v0.z-mu)*rs*ga.z + ba.z;  o0.w = (v0.w-mu)*rs*ga.w + ba.w;
    o1.x = (v1.x-mu)*rs*gb.x + bb.x;  o1.y = (v1.y-mu)*rs*gb.y + bb.y;
    o1.z = (v1.z-mu)*rs*gb.z + bb.z;  o1.w = (v1.w-mu)*rs*gb.w + bb.w;
    float4* dst = (float4*)(d_x + (size_t)tok * EE);
    dst[lane*2] = o0; dst[lane*2+1] = o1;
}

// ---------------- K2: SGEMM gates_x = X @ W_ih^T + b, both dirs fused ----------------
// C[32768, 1600], BM=128, BN=64, BK=8, 256 threads, 8x4 microtile.
__global__ void __launch_bounds__(256) k2_gemm(
    const float* __restrict__ wihf, const float* __restrict__ wihb,
    const float* __restrict__ bf,   const float* __restrict__ bbias)
{
    __shared__ float As[8][128];
    __shared__ float Bs[8][64];
    int m0 = blockIdx.y * 128, n0 = blockIdx.x * 64;
    int tid = threadIdx.x;
    int ar = tid >> 1, ak = (tid & 1) * 4;
    int br = tid >> 2, bk = (tid & 3) * 2;
    int n_b = n0 + br;
    const float* wrow = (n_b < G4) ? (wihf + (size_t)n_b * EE)
                                   : (wihb + (size_t)(n_b - G4) * EE);
    int rmt = tid & 15, cmt = tid >> 4;

    float acc[8][4];
    #pragma unroll
    for (int i = 0; i < 8; ++i)
        #pragma unroll
        for (int j = 0; j < 4; ++j) acc[i][j] = 0.f;

    for (int k0 = 0; k0 < EE; k0 += 8) {
        float4 av = *(const float4*)(d_x + (size_t)(m0 + ar) * EE + k0 + ak);
        float2 bv = *(const float2*)(wrow + k0 + bk);
        __syncthreads();
        As[ak+0][ar] = av.x; As[ak+1][ar] = av.y; As[ak+2][ar] = av.z; As[ak+3][ar] = av.w;
        Bs[bk][br] = bv.x; Bs[bk+1][br] = bv.y;
        __syncthreads();
        #pragma unroll
        for (int kk = 0; kk < 8; ++kk) {
            float a[8];
            float4 bq = *(const float4*)&Bs[kk][cmt * 4];
            #pragma unroll
            for (int i = 0; i < 8; ++i) a[i] = As[kk][rmt + 16 * i];
            #pragma unroll
            for (int i = 0; i < 8; ++i) {
                acc[i][0] += a[i] * bq.x; acc[i][1] += a[i] * bq.y;
                acc[i][2] += a[i] * bq.z; acc[i][3] += a[i] * bq.w;
            }
        }
    }
    #pragma unroll
    for (int j = 0; j < 4; ++j) {
        int n = n0 + cmt * 4 + j;
        int dir = (n >= G4) ? 1 : 0;
        int r = n - dir * G4;
        float bias = dir ? bbias[r] : bf[r];
        float* Gp = d_G + (size_t)dir * (TT * G4 * BB);
        #pragma unroll
        for (int i = 0; i < 8; ++i) {
            int m = m0 + rmt + 16 * i;
            int t = m >> 6, b = m & 63;
            Gp[((size_t)t * G4 + r) * BB + b] = acc[i][j] + bias;
        }
    }
}

// ---------------- K3: persistent bidirectional LSTM with grid barrier ----------------
// Grid = 100 blocks (50 per direction), 128 threads, all resident.
__global__ void __launch_bounds__(128, 1) k3_lstm(
    const float* __restrict__ whhf, const float* __restrict__ whhb,
    const int* __restrict__ seq_len)
{
    extern __shared__ float hsh[];       // [HH][BB] = 51200 B, transposed h_prev
    __shared__ float wsh[16 * HH];       // this block's 16 Whh rows
    __shared__ float gsh[16 * BB];       // gate staging
    __shared__ float csh[HSL * BB];      // cell state slice
    __shared__ int   lensh[BB];

    int tid = threadIdx.x;
    int dir = blockIdx.x / NBD;
    int sl  = blockIdx.x % NBD;
    int j0  = sl * HSL;
    const float* whh = dir ? whhb : whhf;

    for (int i = tid; i < 16 * HH; i += 128) {
        int rr = i / HH, k = i % HH;
        int rglob = (rr >> 2) * HH + j0 + (rr & 3);   // gate q = rr>>2, unit = rr&3
        wsh[i] = whh[(size_t)rglob * HH + k];
    }
    if (tid < BB) lensh[tid] = seq_len[tid];
    csh[tid] = 0.f; csh[tid + 128] = 0.f;

    const float* G = d_G + (size_t)dir * (TT * G4 * BB);
    float* hb = d_hbuf + dir * (2 * HH * BB);

    int bg = tid & 15, rg = tid >> 4;
    int b0 = bg * 4;
    int rr0 = rg * 2, rr1 = rr0 + 1;
    int r0g = (rr0 >> 2) * HH + j0 + (rr0 & 3);
    int r1g = (rr1 >> 2) * HH + j0 + (rr1 & 3);
    __syncthreads();

    for (int st = 0; st < TT; ++st) {
        int t = dir ? (TT - 1 - st) : st;
        int p = st & 1;

        // h_prev (phase p) from L2 into shared
        {
            const float4* src = (const float4*)(hb + p * (HH * BB));
            float4* dst = (float4*)hsh;
            for (int i = tid; i < HH * BB / 4; i += 128) dst[i] = __ldcg(src + i);
        }
        __syncthreads();

        // gates = gx + Whh_slice @ h_prev   (2 rows x 4 batches per thread)
        float4 a0 = *(const float4*)(G + ((size_t)t * G4 + r0g) * BB + b0);
        float4 a1 = *(const float4*)(G + ((size_t)t * G4 + r1g) * BB + b0);
        const float* w0 = wsh + rr0 * HH;
        const float* w1 = wsh + rr1 * HH;
        #pragma unroll 4
        for (int k = 0; k < HH; ++k) {
            float4 hv = *(const float4*)(hsh + k * BB + b0);
            float wa = w0[k], wb = w1[k];
            a0.x += wa * hv.x; a0.y += wa * hv.y; a0.z += wa * hv.z; a0.w += wa * hv.w;
            a1.x += wb * hv.x; a1.y += wb * hv.y; a1.z += wb * hv.z; a1.w += wb * hv.w;
        }
        *(float4*)(gsh + rr0 * BB + b0) = a0;
        *(float4*)(gsh + rr1 * BB + b0) = a1;
        __syncthreads();

        // cell/hidden update: 4 h-units x 64 batches
        #pragma unroll
        for (int u = 0; u < 2; ++u) {
            int idx = tid + u * 128;
            int jj = idx >> 6, b = idx & 63;
            float gi = gsh[jj * BB + b];
            float gf = gsh[(4 + jj) * BB + b];
            float gg = gsh[(8 + jj) * BB + b];
            float go = gsh[(12 + jj) * BB + b];
            float c  = csh[jj * BB + b];
            float cn = sigf(gf) * c + sigf(gi) * tanhf(gg);
            float hn = sigf(go) * tanhf(cn);
            bool valid = (t < lensh[b]);
            float hold = hsh[(j0 + jj) * BB + b];
            float ho = valid ? hn : hold;
            float co = valid ? cn : c;
            csh[jj * BB + b] = co;
            __stcg(hb + (p ^ 1) * (HH * BB) + (j0 + jj) * BB + b, ho);
            d_hall[((size_t)t * BB + b) * (2 * HH) + dir * HH + j0 + jj] = ho;
        }

        // per-direction grid barrier (monotone phase counter; reset by K0)
        __threadfence();
        __syncthreads();
        if (tid == 0) {
            atomicAdd(&d_bar[dir], 1u);
            unsigned tgt = (unsigned)(st + 1) * NBD;
            while (*((volatile unsigned*)&d_bar[dir]) < tgt) { }
            __threadfence();
        }
        __syncthreads();
    }
}

// ---------------- K4: FC + log_softmax (warp per token) ----------------
__global__ void __launch_bounds__(128) k4_fc(
    const float* __restrict__ fcw, const float* __restrict__ fcb)
{
    __shared__ float wsh[CC * 401];   // pad 401 -> conflict-free column reads
    __shared__ float fbsh[CC];
    __shared__ float hs4[4][2 * HH];
    int tid = threadIdx.x;
    for (int i = tid; i < CC * 2 * HH; i += 128) {
        int c = i / (2 * HH), k = i % (2 * HH);
        wsh[c * 401 + k] = fcw[i];
    }
    if (tid < CC) fbsh[tid] = fcb[tid];
    __syncthreads();

    int w = tid >> 5, lane = tid & 31;
    int tok = blockIdx.x * 4 + w;                    // tok = t*64 + b
    for (int k = lane; k < 2 * HH; k += 32) hs4[w][k] = d_hall[(size_t)tok * (2 * HH) + k];
    __syncwarp();

    float acc = -1e30f;
    if (lane < CC) {
        acc = fbsh[lane];
        const float* wr = wsh + lane * 401;
        #pragma unroll 4
        for (int k = 0; k < 2 * HH; ++k) acc += hs4[w][k] * wr[k];
    }
    float m = acc;
    #pragma unroll
    for (int o = 16; o; o >>= 1) m = fmaxf(m, __shfl_xor_sync(~0u, m, o));
    float e = (lane < CC) ? expf(acc - m) : 0.f;
    #pragma unroll
    for (int o = 16; o; o >>= 1) e += __shfl_xor_sync(~0u, e, o);
    float lse = m + logf(e);
    if (lane < CC) {
        int t = tok >> 6, b = tok & 63;
        d_logits[((size_t)b * TT + t) * CC + lane] = acc - lse;
    }
}

// ---------------- K5: CRF NLL, one warp per batch element ----------------
__global__ void __launch_bounds__(32) k5_crf(
    const int* __restrict__ seq_len, const int* __restrict__ target,
    const float* __restrict__ trans, const float* __restrict__ start,
    const float* __restrict__ endsc)
{
    int b = blockIdx.x;
    int lane = threadIdx.x;
    int c = (lane < CC) ? lane : 0;
    int len = seq_len[b];
    const float* L = d_logits + (size_t)b * TT * CC;
    const int* tg = target + (size_t)b * TT;

    float tcol[CC];
    #pragma unroll
    for (int i = 0; i < CC; ++i) tcol[i] = (lane < CC) ? trans[i * CC + c] : 0.f;

    float alpha = (lane < CC) ? (start[c] + L[c]) : -1e30f;

    for (int t = 1; t < len; ++t) {
        float va[CC];
        #pragma unroll
        for (int i = 0; i < CC; ++i)
            va[i] = __shfl_sync(~0u, alpha, i) + tcol[i];
        float m = va[0];
        #pragma unroll
        for (int i = 1; i < CC; ++i) m = fmaxf(m, va[i]);
        float s = 0.f;
        #pragma unroll
        for (int i = 0; i < CC; ++i) s += expf(va[i] - m);
        float emit = (lane < CC) ? L[t * CC + c] : 0.f;
        float nw = m + logf(s) + emit;
        alpha = (lane < CC) ? nw : -1e30f;
    }

    // logZ = lse(alpha + end)
    float v = (lane < CC) ? (alpha + endsc[c]) : -1e30f;
    float m = v;
    #pragma unroll
    for (int o = 16; o; o >>= 1) m = fmaxf(m, __shfl_xor_sync(~0u, m, o));
    float s = expf(v - m);
    if (lane >= CC) s = 0.f;
    #pragma unroll
    for (int o = 16; o; o >>= 1) s += __shfl_xor_sync(~0u, s, o);
    float logZ = m + logf(s);

    // gold score
    float es = 0.f;
    for (int t = lane; t < len; t += 32) es += L[t * CC + tg[t]];
    float ts = 0.f;
    for (int t = lane; t < len - 1; t += 32) ts += trans[tg[t] * CC + tg[t + 1]];
    float g = es + ts;
    #pragma unroll
    for (int o = 16; o; o >>= 1) g += __shfl_xor_sync(~0u, g, o);
    if (lane == 0) {
        float gold = g + start[tg[0]] + endsc[tg[len - 1]];
        d_loss[b] = logZ - gold;
    }
}

// ---------------- K6: mean reduce ----------------
__global__ void __launch_bounds__(64) k6_mean(float* out) {
    __shared__ float sh[64];
    int tid = threadIdx.x;
    sh[tid] = d_loss[tid];
    __syncthreads();
    for (int o = 32; o; o >>= 1) {
        if (tid < o) sh[tid] += sh[tid + o];
        __syncthreads();
    }
    if (tid == 0) out[0] = sh[0] * (1.f / BB);
}

// ---------------- launch ----------------
extern "C" void kernel_launch(void* const* d_in, const int* in_sizes, int n_in,
                              void* d_out, int out_size) {
    const int*   words   = (const int*)d_in[0];
    const int*   seq_len = (const int*)d_in[1];
    const int*   target  = (const int*)d_in[2];
    const float* embed   = (const float*)d_in[3];
    const float* gamma   = (const float*)d_in[4];
    const float* beta    = (const float*)d_in[5];
    const float* wihf    = (const float*)d_in[6];
    const float* whhf    = (const float*)d_in[7];
    const float* bf      = (const float*)d_in[8];
    const float* wihb    = (const float*)d_in[9];
    const float* whhb    = (const float*)d_in[10];
    const float* bb      = (const float*)d_in[11];
    const float* fcw     = (const float*)d_in[12];
    const float* fcb     = (const float*)d_in[13];
    const float* trans   = (const float*)d_in[14];
    const float* startsc = (const float*)d_in[15];
    const float* endsc   = (const float*)d_in[16];
    float* out = (float*)d_out;

    size_t hsmem = (size_t)HH * BB * sizeof(float);   // 51200 B dynamic
    cudaFuncSetAttribute(k3_lstm, cudaFuncAttributeMaxDynamicSharedMemorySize,
                         (int)hsmem);

    k0_init<<<1, 256>>>();
    k1_embed_ln<<<TT * BB / 8, 256>>>(words, embed, gamma, beta);
    {
        dim3 g(2 * G4 / 64, TT * BB / 128);
        k2_gemm<<<g, 256>>>(wihf, wihb, bf, bb);
    }
    k3_lstm<<<2 * NBD, 128, hsmem>>>(whhf, whhb, seq_len);
    k4_fc<<<TT * BB / 4, 128>>>(fcw, fcb);
    k5_crf<<<BB, 32>>>(seq_len, target, trans, startsc, endsc);
    k6_mean<<<1, 64>>>(out);
}